// round 16
// baseline (speedup 1.0000x reference)
#include <cuda_runtime.h>
#include <cuda_fp16.h>
#include <math.h>

// Problem constants
#define BATCH    4
#define HW_IN    (512 * 512)         // gaussians per batch (2^18)
#define W_OUT    1024
#define HW_OUT   (1024 * 1024)
#define N_GAUSS  (BATCH * HW_IN)     // 1,048,576
#define OUT_ELEMS (BATCH * 3 * HW_OUT)
#define N_PIX    (BATCH * HW_OUT)    // 4,194,304
#define NGRP8    (N_PIX / 8)         // final pass: 8 pixels / thread

// Border privatization (proven): ~73% of gaussians clamp to the border ring,
// f32 red.v4 into replicated compact scratch, lane-spread replicas.
// ZERO-INVARIANT: module-load zeroes it; gr_repreduce re-zeros behind itself.
// (Safe for this 4MB hot buffer — unlike the 50MB accumulator in R7 — because
// repreduce touches these exact lines immediately before the next replay's
// scatter, keeping them L2-resident.)
#define R_REP    16
#define BI_N     4096
__device__ float4 g_border[R_REP * BATCH * BI_N];          // 4 MB
__device__ float4 g_bsum[BATCH * BI_N];                    // 256 KB

// Interior accumulator: pixel-interleaved f16x4 (r,g,b,pad) = 8 B/pixel.
// ONE red.global.add.noftz.v2.f16x2 per interior gaussian. 32 MB, L2-resident.
// Explicitly zeroed each launch (zero pass = L2 prefetch for the atomics).
__device__ uint2 g_pacc[N_PIX];                            // 32 MB

#define NZ_PACC   (N_PIX / 2)        // uint4 granules (2,097,152)
#define NZ_HALF   (NZ_PACC / 2)

// ---------------------------------------------------------------------------
// Kernel 1: zero the interleaved accumulator (32 MB), 2 uint4 per thread.
// ---------------------------------------------------------------------------
__global__ void gr_zero_kernel() {
    int i = blockIdx.x * blockDim.x + threadIdx.x;
    uint4 z = make_uint4(0u, 0u, 0u, 0u);
    if (i < NZ_HALF) {
        uint4* p = reinterpret_cast<uint4*>(g_pacc);
        p[i]           = z;
        p[i + NZ_HALF] = z;
    }
}

// ---------------------------------------------------------------------------
// Kernel 2: scatter. Border -> f32 red.v4 replicas. Interior -> single
// vector f16x4 RED into the interleaved accumulator.
// ---------------------------------------------------------------------------
__global__ void gr_scatter_kernel(const float* __restrict__ uv,
                                  const float* __restrict__ pos) {
    int gid = blockIdx.x * blockDim.x + threadIdx.x;
    if (gid >= N_GAUSS) return;
    int b = gid >> 18;            // / HW_IN
    int n = gid & (HW_IN - 1);

    const float* uvb  = uv  + (size_t)b * 14 * HW_IN;
    const float* posb = pos + (size_t)b * 3 * HW_IN;

    float p0 = __ldcs(posb + n);
    float p1 = __ldcs(posb + HW_IN + n);
    float u0 = __ldcs(uvb + n);
    float u1 = __ldcs(uvb + HW_IN + n);
    float uo = __ldcs(uvb + 10 * HW_IN + n);
    float c0 = __ldcs(uvb + 11 * HW_IN + n);
    float c1 = __ldcs(uvb + 12 * HW_IN + n);
    float c2 = __ldcs(uvb + 13 * HW_IN + n);

    float x = p0 + u0;
    float y = p1 + u1;
    float o = 1.0f / (1.0f + __expf(-uo));
    float r  = c0 * o;
    float g  = c1 * o;
    float bl = c2 * o;

    // truncating cast then clamp (matches .astype(int32) + clip)
    int px = (int)((x + 1.0f) * 0.5f * (float)W_OUT);
    int py = (int)((y + 1.0f) * 0.5f * (float)W_OUT);
    px = min(max(px, 0), W_OUT - 1);
    py = min(max(py, 0), W_OUT - 1);

    bool border = (px == 0) | (px == W_OUT - 1) | (py == 0) | (py == W_OUT - 1);
    if (border) {
        // compact border index:
        //   py==0 -> px | py==1023 -> 1024+px | px==0 -> 2048+py | px==1023 -> 3072+py
        int bi = (py == 0)         ? px
               : (py == W_OUT - 1) ? (1024 + px)
               : (px == 0)         ? (2048 + py)
                                   : (3072 + py);
        int rep = gid & (R_REP - 1);   // lane-indexed: same-warp corners spread
        float* p = (float*)&g_border[(rep * BATCH + b) * BI_N + bi];
        asm volatile("red.global.add.v4.f32 [%0], {%1, %2, %3, %4};"
                     :: "l"(p), "f"(r), "f"(g), "f"(bl), "f"(0.0f)
                     : "memory");
    } else {
        size_t idx = (size_t)b * HW_OUT + (size_t)py * W_OUT + px;
        __half2 hrg = __floats2half2_rn(r, g);
        __half2 hb  = __floats2half2_rn(bl, 0.0f);
        unsigned urg = *reinterpret_cast<unsigned*>(&hrg);
        unsigned ub  = *reinterpret_cast<unsigned*>(&hb);
        asm volatile("red.global.add.noftz.v2.f16x2 [%0], {%1, %2};"
                     :: "l"(g_pacc + idx), "r"(urg), "r"(ub)
                     : "memory");
    }
}

// ---------------------------------------------------------------------------
// Kernel 3: collapse border replicas -> g_bsum, re-zero g_border (invariant).
// ---------------------------------------------------------------------------
__global__ void gr_repreduce_kernel() {
    int t = blockIdx.x * blockDim.x + threadIdx.x;   // [0, BATCH*BI_N)
    if (t >= BATCH * BI_N) return;
    float a0 = 0.f, a1 = 0.f, a2 = 0.f;
    float4 z = make_float4(0.f, 0.f, 0.f, 0.f);
    #pragma unroll
    for (int rp = 0; rp < R_REP; ++rp) {
        float4 v = g_border[rp * BATCH * BI_N + t];
        a0 += v.x; a1 += v.y; a2 += v.z;
        g_border[rp * BATCH * BI_N + t] = z;         // restore zero invariant
    }
    g_bsum[t] = make_float4(a0, a1, a2, 0.f);
}

// ---------------------------------------------------------------------------
// Kernel 4: final. Each thread owns 8 consecutive pixels of one row: four
// uint4 loads of interleaved f16x4, register transpose to planar, add f32
// border sums (border pixels' interleaved slots are exactly zero), saturate,
// 6 streaming float4 stores (2 per channel).
// ---------------------------------------------------------------------------
__global__ void gr_final_kernel(float4* __restrict__ out) {
    int i = blockIdx.x * blockDim.x + threadIdx.x;
    if (i >= NGRP8) return;

    int b   = i >> 17;           // 131072 groups per batch
    int e   = i & 0x1FFFF;
    int row = e >> 7;            // 128 groups of 8 per row
    int g8  = e & 127;
    int x0  = g8 << 3;

    size_t pbase = (size_t)b * HW_OUT + ((size_t)row << 10) + x0;
    const uint4* pp = reinterpret_cast<const uint4*>(g_pacc + pbase);
    uint4 q[4];
    q[0] = pp[0]; q[1] = pp[1]; q[2] = pp[2]; q[3] = pp[3];

    float r[8], g[8], bl[8];
    #pragma unroll
    for (int k = 0; k < 4; ++k) {
        float2 t;
        t = __half22float2(*reinterpret_cast<__half2*>(&q[k].x));
        r[2*k] = t.x;   g[2*k] = t.y;
        t = __half22float2(*reinterpret_cast<__half2*>(&q[k].y));
        bl[2*k] = t.x;
        t = __half22float2(*reinterpret_cast<__half2*>(&q[k].z));
        r[2*k+1] = t.x; g[2*k+1] = t.y;
        t = __half22float2(*reinterpret_cast<__half2*>(&q[k].w));
        bl[2*k+1] = t.x;
    }

    const float4* gb = g_bsum + b * BI_N;
    if (row == 0) {
        #pragma unroll
        for (int k = 0; k < 8; ++k) {
            float4 s = gb[x0 + k];
            r[k] += s.x; g[k] += s.y; bl[k] += s.z;
        }
    } else if (row == W_OUT - 1) {
        #pragma unroll
        for (int k = 0; k < 8; ++k) {
            float4 s = gb[1024 + x0 + k];
            r[k] += s.x; g[k] += s.y; bl[k] += s.z;
        }
    } else {
        if (g8 == 0)   { float4 s = gb[2048 + row]; r[0] += s.x; g[0] += s.y; bl[0] += s.z; }
        if (g8 == 127) { float4 s = gb[3072 + row]; r[7] += s.x; g[7] += s.y; bl[7] += s.z; }
    }

    #pragma unroll
    for (int k = 0; k < 8; ++k) {
        r[k]  = __saturatef(r[k]);
        g[k]  = __saturatef(g[k]);
        bl[k] = __saturatef(bl[k]);
    }

    size_t obase = (((size_t)(b * 3) * HW_OUT) + ((size_t)row << 10) + x0) >> 2;
    const size_t plane4 = HW_OUT >> 2;
    __stcs(out + obase,                  make_float4(r[0], r[1], r[2], r[3]));
    __stcs(out + obase + 1,              make_float4(r[4], r[5], r[6], r[7]));
    __stcs(out + obase + plane4,         make_float4(g[0], g[1], g[2], g[3]));
    __stcs(out + obase + plane4 + 1,     make_float4(g[4], g[5], g[6], g[7]));
    __stcs(out + obase + 2 * plane4,     make_float4(bl[0], bl[1], bl[2], bl[3]));
    __stcs(out + obase + 2 * plane4 + 1, make_float4(bl[4], bl[5], bl[6], bl[7]));
}

// ---------------------------------------------------------------------------
extern "C" void kernel_launch(void* const* d_in, const int* in_sizes, int n_in,
                              void* d_out, int out_size) {
    const float* uv  = (const float*)d_in[0];   // [4,14,512,512]
    const float* pos = (const float*)d_in[1];   // [4,3,512,512]
    float* out = (float*)d_out;                 // [4,3,1024,1024]

    const int TPB = 256;

    gr_zero_kernel<<<(NZ_HALF + TPB - 1) / TPB, TPB>>>();
    gr_scatter_kernel<<<(N_GAUSS + 511) / 512, 512>>>(uv, pos);
    gr_repreduce_kernel<<<(BATCH * BI_N + TPB - 1) / TPB, TPB>>>();
    gr_final_kernel<<<(NGRP8 + TPB - 1) / TPB, TPB>>>((float4*)out);
}

// round 17
// speedup vs baseline: 1.0754x; 1.0754x over previous
#include <cuda_runtime.h>
#include <cuda_fp16.h>
#include <math.h>

// Problem constants
#define BATCH    4
#define HW_IN    (512 * 512)         // gaussians per batch (2^18)
#define W_OUT    1024
#define HW_OUT   (1024 * 1024)
#define N_GAUSS  (BATCH * HW_IN)     // 1,048,576
#define OUT_ELEMS (BATCH * 3 * HW_OUT)
#define N_PIX    (BATCH * HW_OUT)    // 4,194,304
#define NGRP4    (N_PIX / 4)         // final pass: 4 pixels / thread

// Border privatization (proven): ~73% of gaussians clamp to the border ring,
// f32 red.v4 into replicated compact scratch, lane-spread replicas.
#define R_REP    16
#define BI_N     4096
__device__ float4 g_border[R_REP * BATCH * BI_N];          // 4 MB
__device__ float4 g_bsum[BATCH * BI_N];                    // 256 KB

// Interior accumulator: pixel-interleaved f16x4 (r,g,b,pad) = 8 B/pixel.
// ONE red.global.add.noftz.v2.f16x2 per interior gaussian (1 op, 1 line).
// 32 MB, L2-resident. Explicitly zeroed each launch (zero = L2 prefetch).
__device__ uint2 g_pacc[N_PIX];                            // 32 MB

// Zeroing extents (uint4 granules): 32 MB pacc + 4 MB border
#define NZ_PACC   (N_PIX / 2)                     // 2,097,152
#define NZ_BORDER (R_REP * BATCH * BI_N)          //   262,144
#define NZ_TOTAL  (NZ_PACC + NZ_BORDER)

// ---------------------------------------------------------------------------
// Kernel 1: zero accumulators (36 MB) — doubles as the L2 prefetch that keeps
// the scatter atomics out of DRAM (proven necessary in R7/R11).
// ---------------------------------------------------------------------------
__global__ void gr_zero_kernel() {
    int i = blockIdx.x * blockDim.x + threadIdx.x;
    uint4 z = make_uint4(0u, 0u, 0u, 0u);
    if (i < NZ_PACC) {
        reinterpret_cast<uint4*>(g_pacc)[i] = z;
    } else if (i < NZ_TOTAL) {
        reinterpret_cast<uint4*>(g_border)[i - NZ_PACC] = z;
    }
}

// ---------------------------------------------------------------------------
// Kernel 2: scatter. Border -> f32 red.v4 replicas. Interior -> single
// vector f16x4 RED into the interleaved accumulator.
// ---------------------------------------------------------------------------
__global__ void gr_scatter_kernel(const float* __restrict__ uv,
                                  const float* __restrict__ pos) {
    int gid = blockIdx.x * blockDim.x + threadIdx.x;
    if (gid >= N_GAUSS) return;
    int b = gid >> 18;            // / HW_IN
    int n = gid & (HW_IN - 1);

    const float* uvb  = uv  + (size_t)b * 14 * HW_IN;
    const float* posb = pos + (size_t)b * 3 * HW_IN;

    float p0 = __ldcs(posb + n);
    float p1 = __ldcs(posb + HW_IN + n);
    float u0 = __ldcs(uvb + n);
    float u1 = __ldcs(uvb + HW_IN + n);
    float uo = __ldcs(uvb + 10 * HW_IN + n);
    float c0 = __ldcs(uvb + 11 * HW_IN + n);
    float c1 = __ldcs(uvb + 12 * HW_IN + n);
    float c2 = __ldcs(uvb + 13 * HW_IN + n);

    float x = p0 + u0;
    float y = p1 + u1;
    float o = 1.0f / (1.0f + __expf(-uo));
    float r  = c0 * o;
    float g  = c1 * o;
    float bl = c2 * o;

    // truncating cast then clamp (matches .astype(int32) + clip)
    int px = (int)((x + 1.0f) * 0.5f * (float)W_OUT);
    int py = (int)((y + 1.0f) * 0.5f * (float)W_OUT);
    px = min(max(px, 0), W_OUT - 1);
    py = min(max(py, 0), W_OUT - 1);

    bool border = (px == 0) | (px == W_OUT - 1) | (py == 0) | (py == W_OUT - 1);
    if (border) {
        // compact border index:
        //   py==0 -> px | py==1023 -> 1024+px | px==0 -> 2048+py | px==1023 -> 3072+py
        int bi = (py == 0)         ? px
               : (py == W_OUT - 1) ? (1024 + px)
               : (px == 0)         ? (2048 + py)
                                   : (3072 + py);
        int rep = gid & (R_REP - 1);   // lane-indexed: same-warp corners spread
        float* p = (float*)&g_border[(rep * BATCH + b) * BI_N + bi];
        asm volatile("red.global.add.v4.f32 [%0], {%1, %2, %3, %4};"
                     :: "l"(p), "f"(r), "f"(g), "f"(bl), "f"(0.0f)
                     : "memory");
    } else {
        size_t idx = (size_t)b * HW_OUT + (size_t)py * W_OUT + px;
        __half2 hrg = __floats2half2_rn(r, g);
        __half2 hb  = __floats2half2_rn(bl, 0.0f);
        unsigned urg = *reinterpret_cast<unsigned*>(&hrg);
        unsigned ub  = *reinterpret_cast<unsigned*>(&hb);
        asm volatile("red.global.add.noftz.v2.f16x2 [%0], {%1, %2};"
                     :: "l"(g_pacc + idx), "r"(urg), "r"(ub)
                     : "memory");
    }
}

// ---------------------------------------------------------------------------
// Kernel 3: collapse border replicas -> g_bsum.
// ---------------------------------------------------------------------------
__global__ void gr_repreduce_kernel() {
    int t = blockIdx.x * blockDim.x + threadIdx.x;   // [0, BATCH*BI_N)
    if (t >= BATCH * BI_N) return;
    float a0 = 0.f, a1 = 0.f, a2 = 0.f;
    #pragma unroll
    for (int rp = 0; rp < R_REP; ++rp) {
        float4 v = g_border[rp * BATCH * BI_N + t];
        a0 += v.x; a1 += v.y; a2 += v.z;
    }
    g_bsum[t] = make_float4(a0, a1, a2, 0.f);
}

// ---------------------------------------------------------------------------
// Kernel 4: final. 4 pixels/thread (R16 showed 8/thread loses TLP to reg
// pressure). pacc loads use __ldcs (read-once, bypass L1 fill) and bsum uses
// __ldg (read-only, heavily shared 256KB). Border pixels' interleaved slots
// are exactly zero — they only receive via the border path.
// ---------------------------------------------------------------------------
__global__ void gr_final_kernel(float4* __restrict__ out) {
    int i = blockIdx.x * blockDim.x + threadIdx.x;
    if (i >= NGRP4) return;

    int b   = i >> 18;           // 262144 groups per batch
    int e   = i & 0x3FFFF;
    int row = e >> 8;            // 256 groups of 4 per row
    int g4  = e & 255;
    int x0  = g4 << 2;

    size_t pbase = (size_t)b * HW_OUT + ((size_t)row << 10) + x0;
    const uint4* pp = reinterpret_cast<const uint4*>(g_pacc + pbase);
    uint4 q0 = __ldcs(pp);       // pixels 0,1: (rg, b_), (rg, b_)
    uint4 q1 = __ldcs(pp + 1);   // pixels 2,3

    float r[4], g[4], bl[4];
    {
        float2 t;
        t = __half22float2(*reinterpret_cast<__half2*>(&q0.x)); r[0]=t.x; g[0]=t.y;
        t = __half22float2(*reinterpret_cast<__half2*>(&q0.y)); bl[0]=t.x;
        t = __half22float2(*reinterpret_cast<__half2*>(&q0.z)); r[1]=t.x; g[1]=t.y;
        t = __half22float2(*reinterpret_cast<__half2*>(&q0.w)); bl[1]=t.x;
        t = __half22float2(*reinterpret_cast<__half2*>(&q1.x)); r[2]=t.x; g[2]=t.y;
        t = __half22float2(*reinterpret_cast<__half2*>(&q1.y)); bl[2]=t.x;
        t = __half22float2(*reinterpret_cast<__half2*>(&q1.z)); r[3]=t.x; g[3]=t.y;
        t = __half22float2(*reinterpret_cast<__half2*>(&q1.w)); bl[3]=t.x;
    }

    const float4* gb = g_bsum + b * BI_N;
    if (row == 0) {
        #pragma unroll
        for (int k = 0; k < 4; ++k) {
            float4 s = __ldg(gb + x0 + k);
            r[k] += s.x; g[k] += s.y; bl[k] += s.z;
        }
    } else if (row == W_OUT - 1) {
        #pragma unroll
        for (int k = 0; k < 4; ++k) {
            float4 s = __ldg(gb + 1024 + x0 + k);
            r[k] += s.x; g[k] += s.y; bl[k] += s.z;
        }
    } else {
        if (g4 == 0)   { float4 s = __ldg(gb + 2048 + row); r[0] += s.x; g[0] += s.y; bl[0] += s.z; }
        if (g4 == 255) { float4 s = __ldg(gb + 3072 + row); r[3] += s.x; g[3] += s.y; bl[3] += s.z; }
    }

    #pragma unroll
    for (int k = 0; k < 4; ++k) {
        r[k]  = __saturatef(r[k]);
        g[k]  = __saturatef(g[k]);
        bl[k] = __saturatef(bl[k]);
    }

    size_t obase = (((size_t)(b * 3) * HW_OUT) + ((size_t)row << 10) + x0) >> 2;
    const size_t plane4 = HW_OUT >> 2;
    __stcs(out + obase,              make_float4(r[0],  r[1],  r[2],  r[3]));
    __stcs(out + obase + plane4,     make_float4(g[0],  g[1],  g[2],  g[3]));
    __stcs(out + obase + 2 * plane4, make_float4(bl[0], bl[1], bl[2], bl[3]));
}

// ---------------------------------------------------------------------------
extern "C" void kernel_launch(void* const* d_in, const int* in_sizes, int n_in,
                              void* d_out, int out_size) {
    const float* uv  = (const float*)d_in[0];   // [4,14,512,512]
    const float* pos = (const float*)d_in[1];   // [4,3,512,512]
    float* out = (float*)d_out;                 // [4,3,1024,1024]

    const int TPB = 256;

    gr_zero_kernel<<<(NZ_TOTAL + TPB - 1) / TPB, TPB>>>();
    gr_scatter_kernel<<<(N_GAUSS + TPB - 1) / TPB, TPB>>>(uv, pos);
    gr_repreduce_kernel<<<(BATCH * BI_N + TPB - 1) / TPB, TPB>>>();
    gr_final_kernel<<<(NGRP4 + TPB - 1) / TPB, TPB>>>((float4*)out);
}